// round 15
// baseline (speedup 1.0000x reference)
#include <cuda_runtime.h>
#include <cuda_fp16.h>
#include <cstdint>

#define N_NODES 20000
#define KN      32
#define CIN     512
#define COUT    512
#define KTOT    1024

// GEMM tiling
#define TM      128
#define TN      128
#define TKH     64                   // halves of K per stage
#define NKT     (KTOT / TKH)         // 16
#define NST     3                    // pipeline stages
#define SH      72                   // smem row stride (halves): 144B, 16B-aligned, conflict-free
#define STG_H   (TM * SH)            // 9216 halves per operand stage

#define NSTRIPE 157                  // ceil(20000/128)
#define NTILES  (NSTRIPE * 4)        // 628
#define GEMM_CTAS 148
#define GEMM_SMEM 118784             // > 110592 actual; forces 1 CTA/SM (2x > 227KB)

#define XCONV_BLKS  2048
#define XCONV_TASKS 1250             // float4 tasks per x-convert block

__device__ __half g_Wh[(size_t)COUT * KTOT];     // [col][k] concat(Wl,Wr), fp16
__device__ __half g_xh[(size_t)N_NODES * CIN];   // x, fp16
__device__ __half g_aggh[(size_t)N_NODES * CIN]; // mean(neigh), fp16
__device__ float  g_bias[COUT];
__device__ unsigned int g_scnt[NSTRIPE];         // per-stripe completed-node counters

__device__ __forceinline__ uint32_t h2u(__half2 h) {
    return *reinterpret_cast<uint32_t*>(&h);
}

// ---------------------------------------------------------------------------
// Kernel 0: W -> fp16 concat layout, bias sum, x -> fp16, counter reset.
// Fully serialized before agg and gemm.
// ---------------------------------------------------------------------------
__global__ void __launch_bounds__(256) convert_kernel(
    const float* __restrict__ x,
    const float* __restrict__ Wl, const float* __restrict__ bl,
    const float* __restrict__ Wr, const float* __restrict__ br)
{
    const int b = blockIdx.x;
    const int t = threadIdx.x;
    if (b < COUT) {
        const int k = t * 4;
        const float* src = (k < CIN) ? (Wl + (size_t)b * CIN + k)
                                     : (Wr + (size_t)b * CIN + (k - CIN));
        float4 v = *reinterpret_cast<const float4*>(src);
        __half2* dst = reinterpret_cast<__half2*>(&g_Wh[(size_t)b * KTOT + k]);
        dst[0] = __floats2half2_rn(v.x, v.y);
        dst[1] = __floats2half2_rn(v.z, v.w);
        if (b == 0) {
            for (int c = t; c < COUT; c += 256) g_bias[c] = bl[c] + br[c];
            if (t < NSTRIPE) g_scnt[t] = 0u;
        }
    } else {
        const int start = (b - COUT) * XCONV_TASKS;
        const int end   = start + XCONV_TASKS;
        for (int i = start + t; i < end; i += 256) {
            float4 v = __ldg(reinterpret_cast<const float4*>(x) + i);
            *reinterpret_cast<uint2*>(&g_xh[(size_t)i * 4]) =
                make_uint2(h2u(__floats2half2_rn(v.x, v.y)),
                           h2u(__floats2half2_rn(v.z, v.w)));
        }
    }
}

// ---------------------------------------------------------------------------
// Kernel 1: per-node mean(neigh) -> fp16, then arrive on stripe counter
// ---------------------------------------------------------------------------
__global__ void __launch_bounds__(128) agg_kernel(const float* __restrict__ neigh)
{
    const int n  = blockIdx.x;
    const int c4 = threadIdx.x;                       // 0..127
    const float4* base = reinterpret_cast<const float4*>(neigh)
                         + (size_t)n * (KN * CIN / 4) + c4;
    float sx = 0.f, sy = 0.f, sz = 0.f, sw = 0.f;
#pragma unroll 8
    for (int k = 0; k < KN; k++) {
        float4 v = __ldg(&base[(size_t)k * (CIN / 4)]);
        sx += v.x; sy += v.y; sz += v.z; sw += v.w;
    }
    const float inv = 1.0f / (float)KN;
    *reinterpret_cast<uint2*>(&g_aggh[(size_t)n * CIN + c4 * 4]) =
        make_uint2(h2u(__floats2half2_rn(sx * inv, sy * inv)),
                   h2u(__floats2half2_rn(sz * inv, sw * inv)));
    __threadfence();
    __syncthreads();
    if (threadIdx.x == 0) atomicAdd(&g_scnt[n >> 7], 1u);
}

// ---------------------------------------------------------------------------
// PTX helpers
// ---------------------------------------------------------------------------
__device__ __forceinline__ void cp_async16_s(uint32_t saddr, const void* g) {
    asm volatile("cp.async.cg.shared.global [%0], [%1], 16;" :: "r"(saddr), "l"(g));
}
__device__ __forceinline__ void cp_commit() {
    asm volatile("cp.async.commit_group;");
}
template <int NW>
__device__ __forceinline__ void cp_wait() {
    asm volatile("cp.async.wait_group %0;" :: "n"(NW));
}
__device__ __forceinline__ void ldsm_x4(uint32_t r[4], uint32_t saddr) {
    asm volatile("ldmatrix.sync.aligned.m8n8.x4.shared.b16 {%0,%1,%2,%3}, [%4];"
                 : "=r"(r[0]), "=r"(r[1]), "=r"(r[2]), "=r"(r[3]) : "r"(saddr));
}
__device__ __forceinline__ void mma_f16(float c[4], const uint32_t a[4],
                                        uint32_t b0, uint32_t b1) {
    asm volatile(
        "mma.sync.aligned.m16n8k16.row.col.f32.f16.f16.f32 "
        "{%0,%1,%2,%3}, {%4,%5,%6,%7}, {%8,%9}, {%0,%1,%2,%3};\n"
        : "+f"(c[0]), "+f"(c[1]), "+f"(c[2]), "+f"(c[3])
        : "r"(a[0]), "r"(a[1]), "r"(a[2]), "r"(a[3]), "r"(b0), "r"(b1));
}

// ---------------------------------------------------------------------------
// Kernel 2: persistent GEMM. 148 CTAs (1/SM via smem pad) loop stripe-major
// over 628 tiles; each tile spin-waits on its stripe's counter.
// ---------------------------------------------------------------------------
__global__ void __launch_bounds__(256, 1) gemm_kernel(float* __restrict__ out)
{
    extern __shared__ __half sm[];
    __half* As = sm;                 // [NST][TM][SH]
    __half* Bs = sm + NST * STG_H;   // [NST][TN][SH]

    const int tid  = threadIdx.x;
    const int lane = tid & 31;
    const int warp = tid >> 5;                  // 0..7
    const int warpM = (warp & 3) * 32;
    const int warpN = (warp >> 2) * 64;

    const uint32_t Abase = (uint32_t)__cvta_generic_to_shared(As);
    const uint32_t Bbase = (uint32_t)__cvta_generic_to_shared(Bs);
    const uint32_t a_lane = (uint32_t)(((lane & 15) * SH + (lane >> 4) * 8) * 2);
    const uint32_t b_lane = (uint32_t)((((lane & 7) + ((lane >> 4) << 3)) * SH
                                        + ((lane >> 3) & 1) * 8) * 2);
    const int g = lane >> 2, t4 = lane & 3;

#pragma unroll 1
    for (int tIdx = blockIdx.x; tIdx < NTILES; tIdx += GEMM_CTAS) {
        const int stripe = tIdx >> 2;
        const int m0 = stripe * TM;
        const int n0 = (tIdx & 3) * TN;

        // wait until this stripe's agg rows are published
        if (tid == 0) {
            const unsigned tgt = (stripe == NSTRIPE - 1)
                                 ? (unsigned)(N_NODES - (NSTRIPE - 1) * TM) : 128u;
            unsigned v;
            while (true) {
                asm volatile("ld.acquire.gpu.u32 %0, [%1];"
                             : "=r"(v) : "l"(&g_scnt[stripe]));
                if (v >= tgt) break;
                __nanosleep(256);
            }
        }
        __syncthreads();

        auto issue_stage = [&](int kt) {
            const int slot = kt % NST;
            const int kb   = kt * TKH;
            const __half* Asrc = (kb < CIN) ? g_xh : g_aggh;
            const int ka = (kb < CIN) ? kb : (kb - CIN);
#pragma unroll
            for (int i = 0; i < 4; i++) {
                const int idx = tid + i * 256;      // 0..1023
                const int r   = idx >> 3;           // 0..127
                const int seg = idx & 7;            // 0..7
                int ar = m0 + r; if (ar > N_NODES - 1) ar = N_NODES - 1;
                cp_async16_s(Abase + (uint32_t)((slot * STG_H + r * SH + seg * 8) * 2),
                             Asrc + (size_t)ar * CIN + ka + seg * 8);
                cp_async16_s(Bbase + (uint32_t)((slot * STG_H + r * SH + seg * 8) * 2),
                             g_Wh + (size_t)(n0 + r) * KTOT + kb + seg * 8);
            }
            cp_commit();
        };

        float acc[2][8][4];
#pragma unroll
        for (int mt = 0; mt < 2; mt++)
#pragma unroll
            for (int nt = 0; nt < 8; nt++)
#pragma unroll
                for (int q = 0; q < 4; q++) acc[mt][nt][q] = 0.f;

        issue_stage(0);
        issue_stage(1);

#pragma unroll 1
        for (int kt = 0; kt < NKT; kt++) {
            if (kt == NKT - 1) cp_wait<0>(); else cp_wait<1>();
            __syncthreads();
            if (kt + 2 < NKT) issue_stage(kt + 2);

            const uint32_t Asl = Abase + (uint32_t)((kt % NST) * STG_H * 2);
            const uint32_t Bsl = Bbase + (uint32_t)((kt % NST) * STG_H * 2);
#pragma unroll
            for (int ks = 0; ks < 4; ks++) {
                const uint32_t ko = (uint32_t)(ks * 16 * 2);
                uint32_t a0[4], a1[4];
                ldsm_x4(a0, Asl + a_lane + ko + (uint32_t)(warpM * SH * 2));
                ldsm_x4(a1, Asl + a_lane + ko + (uint32_t)((warpM + 16) * SH * 2));
#pragma unroll
                for (int p = 0; p < 4; p++) {
                    uint32_t b[4];
                    ldsm_x4(b, Bsl + b_lane + ko + (uint32_t)((warpN + p * 16) * SH * 2));
                    mma_f16(acc[0][2 * p],     a0, b[0], b[1]);
                    mma_f16(acc[1][2 * p],     a1, b[0], b[1]);
                    mma_f16(acc[0][2 * p + 1], a0, b[2], b[3]);
                    mma_f16(acc[1][2 * p + 1], a1, b[2], b[3]);
                }
            }
        }

        // epilogue
#pragma unroll
        for (int mt = 0; mt < 2; mt++)
#pragma unroll
            for (int nt = 0; nt < 8; nt++) {
                const int col = n0 + warpN + nt * 8 + 2 * t4;
                const float b0v = __ldg(&g_bias[col]);
                const float b1v = __ldg(&g_bias[col + 1]);
                const int row0 = m0 + warpM + mt * 16 + g;
                if (row0 < N_NODES)
                    *reinterpret_cast<float2*>(&out[(size_t)row0 * COUT + col]) =
                        make_float2(acc[mt][nt][0] + b0v, acc[mt][nt][1] + b1v);
                const int row1 = row0 + 8;
                if (row1 < N_NODES)
                    *reinterpret_cast<float2*>(&out[(size_t)row1 * COUT + col]) =
                        make_float2(acc[mt][nt][2] + b0v, acc[mt][nt][3] + b1v);
            }
        __syncthreads();   // protect slot 0 before next tile's issue_stage(0)
    }
}

// ---------------------------------------------------------------------------
extern "C" void kernel_launch(void* const* d_in, const int* in_sizes, int n_in,
                              void* d_out, int out_size) {
    const float* x  = (const float*)d_in[0];
    const float* nx = (const float*)d_in[1];
    const float* Wl = (const float*)d_in[2];
    const float* bl = (const float*)d_in[3];
    const float* Wr = (const float*)d_in[4];
    const float* br = (const float*)d_in[5];
    float* out = (float*)d_out;

    // One-time host objects (created on the uncaptured correctness call).
    static cudaStream_t s2 = nullptr;
    static cudaEvent_t  e1 = nullptr, e2 = nullptr;
    static bool init_done = false;
    if (!init_done) {
        cudaStreamCreateWithFlags(&s2, cudaStreamNonBlocking);
        cudaEventCreateWithFlags(&e1, cudaEventDisableTiming);
        cudaEventCreateWithFlags(&e2, cudaEventDisableTiming);
        cudaFuncSetAttribute(gemm_kernel,
                             cudaFuncAttributeMaxDynamicSharedMemorySize, GEMM_SMEM);
        init_done = true;
    }

    // convert on the capture (default) stream
    convert_kernel<<<COUT + XCONV_BLKS, 256>>>(x, Wl, bl, Wr, br);

    // fork: agg on s2, gemm on default stream -> true concurrency in the graph
    cudaEventRecord(e1, 0);
    cudaStreamWaitEvent(s2, e1, 0);
    agg_kernel<<<N_NODES, 128, 0, s2>>>(nx);
    gemm_kernel<<<GEMM_CTAS, 256, GEMM_SMEM>>>(out);

    // join back to the capture stream
    cudaEventRecord(e2, s2);
    cudaStreamWaitEvent(0, e2, 0);
}

// round 17
// speedup vs baseline: 1.0575x; 1.0575x over previous
#include <cuda_runtime.h>
#include <cuda_fp16.h>
#include <cstdint>

#define N_NODES 20000
#define KN      32
#define CIN     512
#define COUT    512
#define KTOT    1024

// GEMM tiling
#define TM      128
#define TN      128
#define TKH     64                   // halves of K per stage
#define NKT     (KTOT / TKH)         // 16
#define NST     3                    // pipeline stages
#define SH      72                   // smem row stride (halves): 144B, 16B-aligned, conflict-free
#define STG_H   (TM * SH)            // 9216 halves per operand stage

#define XCONV_BLKS  2048
#define XCONV_TASKS 1250             // float4 tasks per x-convert block

__device__ __half g_Wh[(size_t)COUT * KTOT];     // [col][k] concat(Wl,Wr), fp16
__device__ __half g_xh[(size_t)N_NODES * CIN];   // x, fp16
__device__ __half g_aggh[(size_t)N_NODES * CIN]; // mean(neigh), fp16
__device__ float  g_bias[COUT];

__device__ __forceinline__ uint32_t h2u(__half2 h) {
    return *reinterpret_cast<uint32_t*>(&h);
}

// ---------------------------------------------------------------------------
// Kernel 0: W -> fp16 concat layout, bias sum, x -> fp16.
// Fully serialized before agg (and therefore before gemm's early launch).
// ---------------------------------------------------------------------------
__global__ void __launch_bounds__(256) convert_kernel(
    const float* __restrict__ x,
    const float* __restrict__ Wl, const float* __restrict__ bl,
    const float* __restrict__ Wr, const float* __restrict__ br)
{
    const int b = blockIdx.x;
    const int t = threadIdx.x;
    if (b < COUT) {
        const int k = t * 4;
        const float* src = (k < CIN) ? (Wl + (size_t)b * CIN + k)
                                     : (Wr + (size_t)b * CIN + (k - CIN));
        float4 v = *reinterpret_cast<const float4*>(src);
        __half2* dst = reinterpret_cast<__half2*>(&g_Wh[(size_t)b * KTOT + k]);
        dst[0] = __floats2half2_rn(v.x, v.y);
        dst[1] = __floats2half2_rn(v.z, v.w);
        if (b == 0)
            for (int c = t; c < COUT; c += 256) g_bias[c] = bl[c] + br[c];
    } else {
        const int start = (b - COUT) * XCONV_TASKS;
        const int end   = start + XCONV_TASKS;
        for (int i = start + t; i < end; i += 256) {
            float4 v = __ldg(reinterpret_cast<const float4*>(x) + i);
            *reinterpret_cast<uint2*>(&g_xh[(size_t)i * 4]) =
                make_uint2(h2u(__floats2half2_rn(v.x, v.y)),
                           h2u(__floats2half2_rn(v.z, v.w)));
        }
    }
}

// ---------------------------------------------------------------------------
// Kernel 1: per-node mean(neigh) -> fp16. Triggers PDL at entry so the gemm
// launches while agg is still streaming (gemm syncs before touching aggh).
// ---------------------------------------------------------------------------
__global__ void __launch_bounds__(128) agg_kernel(const float* __restrict__ neigh)
{
    cudaTriggerProgrammaticLaunchCompletion();
    const int n  = blockIdx.x;
    const int c4 = threadIdx.x;                       // 0..127
    const float4* base = reinterpret_cast<const float4*>(neigh)
                         + (size_t)n * (KN * CIN / 4) + c4;
    float sx = 0.f, sy = 0.f, sz = 0.f, sw = 0.f;
#pragma unroll 8
    for (int k = 0; k < KN; k++) {
        float4 v = __ldg(&base[(size_t)k * (CIN / 4)]);
        sx += v.x; sy += v.y; sz += v.z; sw += v.w;
    }
    const float inv = 1.0f / (float)KN;
    *reinterpret_cast<uint2*>(&g_aggh[(size_t)n * CIN + c4 * 4]) =
        make_uint2(h2u(__floats2half2_rn(sx * inv, sy * inv)),
                   h2u(__floats2half2_rn(sz * inv, sw * inv)));
}

// ---------------------------------------------------------------------------
// PTX helpers
// ---------------------------------------------------------------------------
__device__ __forceinline__ void cp_async16_s(uint32_t saddr, const void* g) {
    asm volatile("cp.async.cg.shared.global [%0], [%1], 16;" :: "r"(saddr), "l"(g));
}
__device__ __forceinline__ void cp_commit() {
    asm volatile("cp.async.commit_group;");
}
template <int NW>
__device__ __forceinline__ void cp_wait() {
    asm volatile("cp.async.wait_group %0;" :: "n"(NW));
}
__device__ __forceinline__ void ldsm_x4(uint32_t r[4], uint32_t saddr) {
    asm volatile("ldmatrix.sync.aligned.m8n8.x4.shared.b16 {%0,%1,%2,%3}, [%4];"
                 : "=r"(r[0]), "=r"(r[1]), "=r"(r[2]), "=r"(r[3]) : "r"(saddr));
}
__device__ __forceinline__ void mma_f16(float c[4], const uint32_t a[4],
                                        uint32_t b0, uint32_t b1) {
    asm volatile(
        "mma.sync.aligned.m16n8k16.row.col.f32.f16.f16.f32 "
        "{%0,%1,%2,%3}, {%4,%5,%6,%7}, {%8,%9}, {%0,%1,%2,%3};\n"
        : "+f"(c[0]), "+f"(c[1]), "+f"(c[2]), "+f"(c[3])
        : "r"(a[0]), "r"(a[1]), "r"(a[2]), "r"(a[3]), "r"(b0), "r"(b1));
}

// ---------------------------------------------------------------------------
// Kernel 2: out = [xh|aggh] @ Wh^T + bias.  128x128 tiles, 3-stage pipeline.
// PDL: chunks 0..7 read xh (ready before agg starts); grid-sync before aggh.
// ---------------------------------------------------------------------------
__global__ void __launch_bounds__(256, 2) gemm_kernel(float* __restrict__ out)
{
    extern __shared__ __half sm[];
    __half* As = sm;                 // [NST][TM][SH]
    __half* Bs = sm + NST * STG_H;   // [NST][TN][SH]

    const int tid  = threadIdx.x;
    const int lane = tid & 31;
    const int warp = tid >> 5;                  // 0..7
    const int warpM = (warp & 3) * 32;
    const int warpN = (warp >> 2) * 64;
    const int m0 = blockIdx.x * TM;
    const int n0 = blockIdx.y * TN;

    const uint32_t Abase = (uint32_t)__cvta_generic_to_shared(As);
    const uint32_t Bbase = (uint32_t)__cvta_generic_to_shared(Bs);
    const uint32_t a_lane = (uint32_t)(((lane & 15) * SH + (lane >> 4) * 8) * 2);
    const uint32_t b_lane = (uint32_t)((((lane & 7) + ((lane >> 4) << 3)) * SH
                                        + ((lane >> 3) & 1) * 8) * 2);

    auto issue_stage = [&](int kt) {
        const int slot = kt % NST;
        const int kb   = kt * TKH;
        const __half* Asrc = (kb < CIN) ? g_xh : g_aggh;
        const int ka = (kb < CIN) ? kb : (kb - CIN);
#pragma unroll
        for (int i = 0; i < 4; i++) {
            const int idx = tid + i * 256;      // 0..1023
            const int r   = idx >> 3;           // 0..127
            const int seg = idx & 7;            // 0..7
            int ar = m0 + r; if (ar > N_NODES - 1) ar = N_NODES - 1;
            cp_async16_s(Abase + (uint32_t)((slot * STG_H + r * SH + seg * 8) * 2),
                         Asrc + (size_t)ar * CIN + ka + seg * 8);
            cp_async16_s(Bbase + (uint32_t)((slot * STG_H + r * SH + seg * 8) * 2),
                         g_Wh + (size_t)(n0 + r) * KTOT + kb + seg * 8);
        }
        cp_commit();
    };

    float acc[2][8][4];
#pragma unroll
    for (int mt = 0; mt < 2; mt++)
#pragma unroll
        for (int nt = 0; nt < 8; nt++)
#pragma unroll
            for (int q = 0; q < 4; q++) acc[mt][nt][q] = 0.f;

    issue_stage(0);
    issue_stage(1);

#pragma unroll 1
    for (int kt = 0; kt < NKT; kt++) {
        if (kt == NKT - 1) cp_wait<0>(); else cp_wait<1>();
        __syncthreads();
        // first prefetch that touches aggh is chunk 8 (kb=512): wait for agg.
        if (kt + 2 == CIN / TKH) cudaGridDependencySynchronize();
        if (kt + 2 < NKT) issue_stage(kt + 2);

        const uint32_t Asl = Abase + (uint32_t)((kt % NST) * STG_H * 2);
        const uint32_t Bsl = Bbase + (uint32_t)((kt % NST) * STG_H * 2);
#pragma unroll
        for (int ks = 0; ks < 4; ks++) {
            const uint32_t ko = (uint32_t)(ks * 16 * 2);
            uint32_t a0[4], a1[4];
            ldsm_x4(a0, Asl + a_lane + ko + (uint32_t)(warpM * SH * 2));
            ldsm_x4(a1, Asl + a_lane + ko + (uint32_t)((warpM + 16) * SH * 2));
#pragma unroll
            for (int p = 0; p < 4; p++) {
                uint32_t b[4];
                ldsm_x4(b, Bsl + b_lane + ko + (uint32_t)((warpN + p * 16) * SH * 2));
                mma_f16(acc[0][2 * p],     a0, b[0], b[1]);
                mma_f16(acc[1][2 * p],     a1, b[0], b[1]);
                mma_f16(acc[0][2 * p + 1], a0, b[2], b[3]);
                mma_f16(acc[1][2 * p + 1], a1, b[2], b[3]);
            }
        }
    }

    // epilogue
    const int g = lane >> 2, t4 = lane & 3;
#pragma unroll
    for (int mt = 0; mt < 2; mt++)
#pragma unroll
        for (int nt = 0; nt < 8; nt++) {
            const int col = n0 + warpN + nt * 8 + 2 * t4;
            const float b0v = __ldg(&g_bias[col]);
            const float b1v = __ldg(&g_bias[col + 1]);
            const int row0 = m0 + warpM + mt * 16 + g;
            if (row0 < N_NODES)
                *reinterpret_cast<float2*>(&out[(size_t)row0 * COUT + col]) =
                    make_float2(acc[mt][nt][0] + b0v, acc[mt][nt][1] + b1v);
            const int row1 = row0 + 8;
            if (row1 < N_NODES)
                *reinterpret_cast<float2*>(&out[(size_t)row1 * COUT + col]) =
                    make_float2(acc[mt][nt][2] + b0v, acc[mt][nt][3] + b1v);
        }
}

// ---------------------------------------------------------------------------
extern "C" void kernel_launch(void* const* d_in, const int* in_sizes, int n_in,
                              void* d_out, int out_size) {
    const float* x  = (const float*)d_in[0];
    const float* nx = (const float*)d_in[1];
    const float* Wl = (const float*)d_in[2];
    const float* bl = (const float*)d_in[3];
    const float* Wr = (const float*)d_in[4];
    const float* br = (const float*)d_in[5];
    float* out = (float*)d_out;

    convert_kernel<<<COUT + XCONV_BLKS, 256>>>(x, Wl, bl, Wr, br);
    agg_kernel<<<N_NODES, 128>>>(nx);

    const int smem_bytes = NST * 2 * STG_H * (int)sizeof(__half);  // 110592
    cudaFuncSetAttribute(gemm_kernel,
                         cudaFuncAttributeMaxDynamicSharedMemorySize, smem_bytes);

    // PDL launch: gemm launches once all agg CTAs have started (trigger),
    // runs its x-half, and grid-syncs before reading aggh.
    cudaLaunchConfig_t cfg = {};
    cfg.gridDim  = dim3((N_NODES + TM - 1) / TM, COUT / TN, 1);    // 157 x 4
    cfg.blockDim = dim3(256, 1, 1);
    cfg.dynamicSmemBytes = smem_bytes;
    cfg.stream = 0;
    cudaLaunchAttribute attrs[1];
    attrs[0].id = cudaLaunchAttributeProgrammaticStreamSerialization;
    attrs[0].val.programmaticStreamSerializationAllowed = 1;
    cfg.attrs = attrs;
    cfg.numAttrs = 1;
    cudaLaunchKernelEx(&cfg, gemm_kernel, out);
}